// round 1
// baseline (speedup 1.0000x reference)
#include <cuda_runtime.h>
#include <math.h>

// Problem constants
#define NB 64
#define NS 512
#define NPIX (NS * NS)          // 262144
#define HF_COUNT 245760.0f      // 512*512 - 128*128

// -------- scratch (device globals; no allocation allowed) --------
__device__ float2 g_A[NB * NPIX];   // 134 MB: packed complex, row-FFT in place
__device__ float2 g_Bf[NB * NPIX];  // 134 MB: transposed, col-FFT in place
__device__ float2 g_tw[512];        // twiddles w^k = exp(-2*pi*i*k/512)
__device__ float  g_part[NB][8];    // per-(batch, u-chunk) partial sums (deterministic)

// -------- complex helpers --------
static __device__ __forceinline__ float2 cadd(float2 a, float2 b) { return make_float2(a.x + b.x, a.y + b.y); }
static __device__ __forceinline__ float2 csub(float2 a, float2 b) { return make_float2(a.x - b.x, a.y - b.y); }
static __device__ __forceinline__ float2 cmul(float2 a, float2 w) {
    return make_float2(fmaf(a.x, w.x, -a.y * w.y), fmaf(a.x, w.y, a.y * w.x));
}

// DFT-8 (DIF internally, output mapped to natural order X[0..7])
static __device__ __forceinline__ void dft8(const float2 a[8], float2 X[8]) {
    const float r = 0.70710678118654752440f;
    float2 s0 = cadd(a[0], a[4]), d0 = csub(a[0], a[4]);
    float2 s1 = cadd(a[1], a[5]), d1 = csub(a[1], a[5]);
    float2 s2 = cadd(a[2], a[6]), d2 = csub(a[2], a[6]);
    float2 s3 = cadd(a[3], a[7]), d3 = csub(a[3], a[7]);
    // twiddles: d1 *= w8^1, d2 *= w8^2 (= -i), d3 *= w8^3
    float2 d1t = make_float2(r * (d1.x + d1.y), r * (d1.y - d1.x));
    float2 d2t = make_float2(d2.y, -d2.x);
    float2 d3t = make_float2(r * (d3.y - d3.x), -r * (d3.x + d3.y));
    // even half: DFT4 of (s0..s3) -> X[0],X[2],X[4],X[6]
    float2 u0 = cadd(s0, s2), u2 = csub(s0, s2);
    float2 u1 = cadd(s1, s3);
    float2 u3t = csub(s1, s3);
    float2 u3 = make_float2(u3t.y, -u3t.x); // * (-i)
    X[0] = cadd(u0, u1);  X[4] = csub(u0, u1);
    X[2] = cadd(u2, u3);  X[6] = csub(u2, u3);
    // odd half: DFT4 of (d0, d1t, d2t, d3t) -> X[1],X[3],X[5],X[7]
    float2 v0 = cadd(d0, d2t), v2 = csub(d0, d2t);
    float2 v1 = cadd(d1t, d3t);
    float2 v3t = csub(d1t, d3t);
    float2 v3 = make_float2(v3t.y, -v3t.x); // * (-i)
    X[1] = cadd(v0, v1);  X[5] = csub(v0, v1);
    X[3] = cadd(v2, v3);  X[7] = csub(v2, v3);
}

// -------- K0: twiddle init (runs every launch; trivial cost) --------
__global__ void k_init() {
    int t = threadIdx.x;
    if (t < 512) {
        double ang = -6.2831853071795864769252867665590058 * (double)t / 512.0;
        g_tw[t] = make_float2((float)cos(ang), (float)sin(ang));
    }
}

// -------- K1: grayscale + pack gen (real) / tgt (imag) --------
static __device__ __forceinline__ float gray01(float r, float g, float b) {
    return (r * 0.299f + g * 0.587f + b * 0.114f + 1.0f) * 0.5f;
}

__global__ void k_gray(const float* __restrict__ gen, const float* __restrict__ tgt) {
    unsigned i = blockIdx.x * 256u + threadIdx.x;     // 0 .. 4194303 (4 px each)
    unsigned b = i >> 16;                             // 65536 quads per batch
    unsigned p = (i & 65535u) << 2;                   // pixel index within batch
    size_t base = (size_t)b * (3u * NPIX) + p;
    float4 r0 = *(const float4*)(gen + base);
    float4 g0 = *(const float4*)(gen + base + NPIX);
    float4 b0 = *(const float4*)(gen + base + 2u * NPIX);
    float4 r1 = *(const float4*)(tgt + base);
    float4 g1 = *(const float4*)(tgt + base + NPIX);
    float4 b1 = *(const float4*)(tgt + base + 2u * NPIX);

    float a0 = gray01(r0.x, g0.x, b0.x), a1 = gray01(r0.y, g0.y, b0.y);
    float a2 = gray01(r0.z, g0.z, b0.z), a3 = gray01(r0.w, g0.w, b0.w);
    float t0 = gray01(r1.x, g1.x, b1.x), t1 = gray01(r1.y, g1.y, b1.y);
    float t2 = gray01(r1.z, g1.z, b1.z), t3 = gray01(r1.w, g1.w, b1.w);

    float4* o4 = (float4*)(g_A + (size_t)b * NPIX + p);
    o4[0] = make_float4(a0, t0, a1, t1);
    o4[1] = make_float4(a2, t2, a3, t3);
}

// -------- K2/K4: batched 512-pt FFT along contiguous rows (in place) --------
// Radix-8 Stockham, 3 stages. 64 threads per FFT, 4 FFTs per 256-thread block.
// Smem ping is a single padded buffer with 2 syncs per exchange.
#define PADIDX(i) ((i) + ((i) >> 3))

template <int WHICH>
__global__ void __launch_bounds__(256) k_fft_rows() {
    float2* data = WHICH ? g_Bf : g_A;
    __shared__ float2 tw[512];
    __shared__ float2 buf[4][576];   // 512 + 64 pad per FFT

    int tid = threadIdx.x;
    for (int i = tid; i < 512; i += 256) tw[i] = g_tw[i];

    int f = tid >> 6;
    int j = tid & 63;
    size_t row = (size_t)blockIdx.x * 4 + f;   // 32768 rows total
    float2* rp = data + row * NS;

    float2 a[8], X[8];
    #pragma unroll
    for (int p = 0; p < 8; p++) a[p] = rp[p * 64 + j];

    // stage 0 (L=1): no twiddle, write idx = j*8 + q
    dft8(a, X);
    #pragma unroll
    for (int q = 0; q < 8; q++) { int idx = j * 8 + q; buf[f][PADIDX(idx)] = X[q]; }
    __syncthreads();   // also covers twiddle table load

    // stage 1 (L=8): read p*64+j, twiddle w^(8*p*k), write blk*64 + q*8 + k
    #pragma unroll
    for (int p = 0; p < 8; p++) { int idx = p * 64 + j; a[p] = buf[f][PADIDX(idx)]; }
    __syncthreads();
    int k1 = j & 7, b1 = j >> 3;
    #pragma unroll
    for (int p = 1; p < 8; p++) a[p] = cmul(a[p], tw[(p * k1) << 3]);
    dft8(a, X);
    #pragma unroll
    for (int q = 0; q < 8; q++) { int idx = b1 * 64 + q * 8 + k1; buf[f][PADIDX(idx)] = X[q]; }
    __syncthreads();

    // stage 2 (L=64): read p*64+j, twiddle w^(p*j), write global q*64 + j
    #pragma unroll
    for (int p = 0; p < 8; p++) { int idx = p * 64 + j; a[p] = buf[f][PADIDX(idx)]; }
    #pragma unroll
    for (int p = 1; p < 8; p++) a[p] = cmul(a[p], tw[p * j]);
    dft8(a, X);
    #pragma unroll
    for (int q = 0; q < 8; q++) rp[q * 64 + j] = X[q];
}

// -------- K3: per-batch 512x512 transpose (g_A -> g_Bf) --------
__global__ void k_transpose() {
    __shared__ float2 tile[32][33];
    int b = blockIdx.z;
    const float2* src = g_A + (size_t)b * NPIX;
    float2* dst = g_Bf + (size_t)b * NPIX;
    int x = blockIdx.x * 32 + threadIdx.x;
    int y0 = blockIdx.y * 32 + threadIdx.y;
    #pragma unroll
    for (int i = 0; i < 32; i += 8)
        tile[threadIdx.y + i][threadIdx.x] = src[(size_t)(y0 + i) * NS + x];
    __syncthreads();
    int x2 = blockIdx.y * 32 + threadIdx.x;
    int y2 = blockIdx.x * 32 + threadIdx.y;
    #pragma unroll
    for (int i = 0; i < 32; i += 8)
        dst[(size_t)(y2 + i) * NS + x2] = tile[threadIdx.x][threadIdx.y + i];
}

// -------- K5: PSD separation + masked log sum (per batch, per u-chunk) --------
// Z = FFT2(gen + i*tgt). F_gen(k) = 0.5*(Z(k)+conj(Z(-k))), F_tgt(k) = -0.5i*(Z(k)-conj(Z(-k)))
// Mask (unshifted coords): EXCLUDE iff (u<64 || u>=448) && (v<64 || v>=448)
__global__ void __launch_bounds__(256) k_psd() {
    int b = blockIdx.x;       // batch
    int uc = blockIdx.y;      // u chunk (64 u's)
    const float2* Fb = g_Bf + (size_t)b * NPIX;

    float acc = 0.0f;
    for (int e = threadIdx.x; e < 64 * NS; e += 256) {
        int u = uc * 64 + (e >> 9);
        int v = e & 511;
        bool lowu = (u < 64) | (u >= 448);
        bool lowv = (v < 64) | (v >= 448);
        if (lowu & lowv) continue;   // low-frequency box: masked out

        float2 z1 = Fb[u * NS + v];
        int u2 = (NS - u) & 511, v2 = (NS - v) & 511;
        float2 z2 = Fb[u2 * NS + v2];

        float ra = 0.5f * (z1.x + z2.x), ia = 0.5f * (z1.y - z2.y);
        float rb = 0.5f * (z1.y + z2.y), ib = 0.5f * (z2.x - z1.x);
        float pa = fmaf(ra, ra, ia * ia) + 1e-10f;
        float pb = fmaf(rb, rb, ib * ib) + 1e-10f;
        acc += __log2f(pa) - __log2f(pb);   // log10 factor applied at the end
    }

    __shared__ float red[256];
    red[threadIdx.x] = acc;
    __syncthreads();
    #pragma unroll
    for (int s = 128; s > 0; s >>= 1) {
        if (threadIdx.x < s) red[threadIdx.x] += red[threadIdx.x + s];
        __syncthreads();
    }
    if (threadIdx.x == 0) g_part[b][uc] = red[0];   // no atomics -> deterministic
}

// -------- K6: finalize: loss = mean_b |D_b| * log10(2) / count --------
__global__ void k_final(float* __restrict__ out) {
    int t = threadIdx.x;   // 64 threads
    float d = 0.0f;
    #pragma unroll
    for (int uc = 0; uc < 8; uc++) d += g_part[t][uc];
    __shared__ float red[64];
    red[t] = fabsf(d);
    __syncthreads();
    #pragma unroll
    for (int s = 32; s > 0; s >>= 1) {
        if (t < s) red[t] += red[t + s];
        __syncthreads();
    }
    if (t == 0) out[0] = red[0] * (0.30102999566398119521f / (HF_COUNT * 64.0f));
}

// -------- launch --------
extern "C" void kernel_launch(void* const* d_in, const int* in_sizes, int n_in,
                              void* d_out, int out_size) {
    const float* gen = (const float*)d_in[0];
    const float* tgt = (const float*)d_in[1];
    float* out = (float*)d_out;
    (void)in_sizes; (void)n_in; (void)out_size;

    k_init<<<1, 512>>>();
    k_gray<<<16384, 256>>>(gen, tgt);                 // 4,194,304 threads, 4 px each
    k_fft_rows<0><<<NB * NS / 4, 256>>>();            // row FFT on g_A (in place)
    {
        dim3 g(16, 16, NB), t(32, 8);
        k_transpose<<<g, t>>>();                      // g_A -> g_Bf (transposed)
    }
    k_fft_rows<1><<<NB * NS / 4, 256>>>();            // "column" FFT on g_Bf (in place)
    {
        dim3 g(NB, 8);
        k_psd<<<g, 256>>>();
    }
    k_final<<<1, 64>>>(out);
}

// round 2
// speedup vs baseline: 1.7231x; 1.7231x over previous
#include <cuda_runtime.h>
#include <math.h>

// Problem constants
#define NB 64
#define NS 512
#define NPIX (NS * NS)          // 262144
#define HF_COUNT 245760.0f      // 512*512 - 128*128

// -------- scratch (device globals; no allocation allowed) --------
__device__ float2 g_Bf[NB * NPIX];   // 134 MB: pass-1 output, TRANSPOSED (row = u freq, col = y)
__device__ float2 g_tw[512];         // twiddles w^k = exp(-2*pi*i*k/512)
__device__ float  g_part[NB][256];   // per-(batch, row-pair) partial sums (deterministic)

// -------- complex helpers --------
static __device__ __forceinline__ float2 cadd(float2 a, float2 b) { return make_float2(a.x + b.x, a.y + b.y); }
static __device__ __forceinline__ float2 csub(float2 a, float2 b) { return make_float2(a.x - b.x, a.y - b.y); }
static __device__ __forceinline__ float2 cmul(float2 a, float2 w) {
    return make_float2(fmaf(a.x, w.x, -a.y * w.y), fmaf(a.x, w.y, a.y * w.x));
}

// DFT-8 (DIF internally, output in natural order X[0..7])
static __device__ __forceinline__ void dft8(const float2 a[8], float2 X[8]) {
    const float r = 0.70710678118654752440f;
    float2 s0 = cadd(a[0], a[4]), d0 = csub(a[0], a[4]);
    float2 s1 = cadd(a[1], a[5]), d1 = csub(a[1], a[5]);
    float2 s2 = cadd(a[2], a[6]), d2 = csub(a[2], a[6]);
    float2 s3 = cadd(a[3], a[7]), d3 = csub(a[3], a[7]);
    float2 d1t = make_float2(r * (d1.x + d1.y), r * (d1.y - d1.x));
    float2 d2t = make_float2(d2.y, -d2.x);
    float2 d3t = make_float2(r * (d3.y - d3.x), -r * (d3.x + d3.y));
    float2 u0 = cadd(s0, s2), u2 = csub(s0, s2);
    float2 u1 = cadd(s1, s3);
    float2 u3t = csub(s1, s3);
    float2 u3 = make_float2(u3t.y, -u3t.x);
    X[0] = cadd(u0, u1);  X[4] = csub(u0, u1);
    X[2] = cadd(u2, u3);  X[6] = csub(u2, u3);
    float2 v0 = cadd(d0, d2t), v2 = csub(d0, d2t);
    float2 v1 = cadd(d1t, d3t);
    float2 v3t = csub(d1t, d3t);
    float2 v3 = make_float2(v3t.y, -v3t.x);
    X[1] = cadd(v0, v1);  X[5] = csub(v0, v1);
    X[3] = cadd(v2, v3);  X[7] = csub(v2, v3);
}

// -------- K0: twiddle init --------
__global__ void k_init() {
    int t = threadIdx.x;
    if (t < 512) {
        double ang = -6.2831853071795864769252867665590058 * (double)t / 512.0;
        g_tw[t] = make_float2((float)cos(ang), (float)sin(ang));
    }
}

static __device__ __forceinline__ float gray01(float r, float g, float b) {
    return (r * 0.299f + g * 0.587f + b * 0.114f + 1.0f) * 0.5f;
}

#define PADIDX(i) ((i) + ((i) >> 3))

// -------- K1: fused gray + row-FFT + transposed write --------
// 8 FFTs (8 consecutive image rows of one batch) per 512-thread block.
// Output element u of row y goes to g_Bf[b][u*512 + y] via a smem transpose
// tile so global stores are 64B-contiguous per 8 lanes (sector-complete).
__global__ void __launch_bounds__(512) k_fft1(const float* __restrict__ gen,
                                              const float* __restrict__ tgt) {
    __shared__ float2 tw[512];
    __shared__ float2 buf[8][576];   // 4608 float2; reused as tile[512][9] (=4608) at the end

    int tid = threadIdx.x;
    for (int i = tid; i < 512; i += 512) tw[i] = g_tw[i];

    int f = tid >> 6;                 // FFT id within block (0..7)
    int j = tid & 63;                 // lane within FFT
    int b  = blockIdx.x >> 6;         // 64 blocks per batch
    int y0 = (blockIdx.x & 63) << 3;  // first image row of this block
    int y  = y0 + f;

    size_t gbase = (size_t)b * (3u * NPIX) + (size_t)y * NS;
    const float* gp = gen + gbase;
    const float* tp = tgt + gbase;

    float2 a[8], X[8];
    #pragma unroll
    for (int p = 0; p < 8; p++) {
        int x = p * 64 + j;
        float g0 = gp[x], g1 = gp[x + NPIX], g2 = gp[x + 2 * NPIX];
        float t0 = tp[x], t1 = tp[x + NPIX], t2 = tp[x + 2 * NPIX];
        a[p] = make_float2(gray01(g0, g1, g2), gray01(t0, t1, t2));
    }

    // stage 0 (L=1)
    dft8(a, X);
    #pragma unroll
    for (int q = 0; q < 8; q++) { int idx = j * 8 + q; buf[f][PADIDX(idx)] = X[q]; }
    __syncthreads();

    // stage 1 (L=8)
    #pragma unroll
    for (int p = 0; p < 8; p++) { int idx = p * 64 + j; a[p] = buf[f][PADIDX(idx)]; }
    __syncthreads();
    int k1 = j & 7, b1 = j >> 3;
    #pragma unroll
    for (int p = 1; p < 8; p++) a[p] = cmul(a[p], tw[(p * k1) << 3]);
    dft8(a, X);
    #pragma unroll
    for (int q = 0; q < 8; q++) { int idx = b1 * 64 + q * 8 + k1; buf[f][PADIDX(idx)] = X[q]; }
    __syncthreads();

    // stage 2 (L=64)
    #pragma unroll
    for (int p = 0; p < 8; p++) { int idx = p * 64 + j; a[p] = buf[f][PADIDX(idx)]; }
    __syncthreads();   // all buf reads done; safe to reuse as transpose tile
    #pragma unroll
    for (int p = 1; p < 8; p++) a[p] = cmul(a[p], tw[p * j]);
    dft8(a, X);

    // stage result into transpose tile: tile[u][f], padded stride 9
    float2* tile = &buf[0][0];
    #pragma unroll
    for (int q = 0; q < 8; q++) { int u = q * 64 + j; tile[u * 9 + f] = X[q]; }
    __syncthreads();

    // coalesced transposed write: lanes cover 8 consecutive y per u (64B chunks)
    int yo = tid & 7;          // y offset within block
    int ub = tid >> 3;         // 0..63
    float2* dst = g_Bf + (size_t)b * NPIX + y0 + yo;
    #pragma unroll
    for (int i = 0; i < 8; i++) {
        int u = ub + i * 64;
        dst[(size_t)u * NS] = tile[u * 9 + yo];
    }
}

// -------- K2: column FFT on conjugate-partner row pairs + fused PSD --------
// Block (v, b): FFTs g_Bf rows rA=v and rB=(v==0?256:512-v) (2 FFTs, 128 thr).
// Z(u,v) pairs with Z(512-u,512-v): both rows live in smem `res`, so the PSD
// separation + masked log sum happens in-block. No global writeback of Z2.
__global__ void __launch_bounds__(128) k_fft2_psd() {
    __shared__ float2 tw[512];
    __shared__ float2 buf[2][576];
    __shared__ float2 res[2][512];
    __shared__ float  red[128];

    int tid = threadIdx.x;
    for (int i = tid; i < 512; i += 128) tw[i] = g_tw[i];

    int v = blockIdx.x;            // 0..255
    int b = blockIdx.y;            // batch
    int f = tid >> 6;              // 0 or 1
    int j = tid & 63;
    int rA = v;
    int rB = (v == 0) ? 256 : 512 - v;
    int r  = f ? rB : rA;

    const float2* rp = g_Bf + (size_t)b * NPIX + (size_t)r * NS;

    float2 a[8], X[8];
    #pragma unroll
    for (int p = 0; p < 8; p++) a[p] = rp[p * 64 + j];

    dft8(a, X);
    #pragma unroll
    for (int q = 0; q < 8; q++) { int idx = j * 8 + q; buf[f][PADIDX(idx)] = X[q]; }
    __syncthreads();

    #pragma unroll
    for (int p = 0; p < 8; p++) { int idx = p * 64 + j; a[p] = buf[f][PADIDX(idx)]; }
    __syncthreads();
    int k1 = j & 7, b1 = j >> 3;
    #pragma unroll
    for (int p = 1; p < 8; p++) a[p] = cmul(a[p], tw[(p * k1) << 3]);
    dft8(a, X);
    #pragma unroll
    for (int q = 0; q < 8; q++) { int idx = b1 * 64 + q * 8 + k1; buf[f][PADIDX(idx)] = X[q]; }
    __syncthreads();

    #pragma unroll
    for (int p = 0; p < 8; p++) { int idx = p * 64 + j; a[p] = buf[f][PADIDX(idx)]; }
    #pragma unroll
    for (int p = 1; p < 8; p++) a[p] = cmul(a[p], tw[p * j]);
    dft8(a, X);
    #pragma unroll
    for (int q = 0; q < 8; q++) res[f][q * 64 + j] = X[q];
    __syncthreads();

    // PSD pairing. Rows rA and rB are fully covered by this block (each grid
    // element computed exactly once across blocks). v==0: rows 0 and 256 are
    // self-paired.
    bool self = (v == 0);
    bool lowA = (rA < 64) | (rA >= 448);
    bool lowB = (rB < 64) | (rB >= 448);

    float acc = 0.0f;
    #pragma unroll
    for (int it = 0; it < 8; it++) {
        int i = it * 128 + tid;        // 0..1023
        int s = i >> 9;                // 0 -> row rA, 1 -> row rB
        int e = i & 511;               // element (y-frequency)
        bool lowr = s ? lowB : lowA;
        bool lowe = (e < 64) | (e >= 448);
        if (lowr & lowe) continue;     // low-frequency box masked out

        float2 z1 = res[s][e];
        int ps = self ? s : (1 - s);
        float2 z2 = res[ps][(512 - e) & 511];

        float ra = 0.5f * (z1.x + z2.x), ia = 0.5f * (z1.y - z2.y);
        float rb = 0.5f * (z1.y + z2.y), ib = 0.5f * (z2.x - z1.x);
        float pa = fmaf(ra, ra, ia * ia) + 1e-10f;
        float pb = fmaf(rb, rb, ib * ib) + 1e-10f;
        acc += __log2f(pa) - __log2f(pb);   // log10 factor applied at the end
    }

    red[tid] = acc;
    __syncthreads();
    #pragma unroll
    for (int s2 = 64; s2 > 0; s2 >>= 1) {
        if (tid < s2) red[tid] += red[tid + s2];
        __syncthreads();
    }
    if (tid == 0) g_part[b][v] = red[0];   // no atomics -> deterministic
}

// -------- K3: finalize: loss = mean_b |D_b| * log10(2) / count --------
__global__ void k_final(float* __restrict__ out) {
    int t = threadIdx.x;   // 64 threads
    float d = 0.0f;
    for (int i = 0; i < 256; i++) d += g_part[t][i];
    __shared__ float red[64];
    red[t] = fabsf(d);
    __syncthreads();
    #pragma unroll
    for (int s = 32; s > 0; s >>= 1) {
        if (t < s) red[t] += red[t + s];
        __syncthreads();
    }
    if (t == 0) out[0] = red[0] * (0.30102999566398119521f / (HF_COUNT * 64.0f));
}

// -------- launch --------
extern "C" void kernel_launch(void* const* d_in, const int* in_sizes, int n_in,
                              void* d_out, int out_size) {
    const float* gen = (const float*)d_in[0];
    const float* tgt = (const float*)d_in[1];
    float* out = (float*)d_out;
    (void)in_sizes; (void)n_in; (void)out_size;

    k_init<<<1, 512>>>();
    k_fft1<<<NB * 64, 512>>>(gen, tgt);        // fused gray + row FFT + transpose
    {
        dim3 g(256, NB);
        k_fft2_psd<<<g, 128>>>();              // column FFT + fused PSD
    }
    k_final<<<1, 64>>>(out);
}

// round 3
// speedup vs baseline: 1.8799x; 1.0910x over previous
#include <cuda_runtime.h>
#include <cuda_fp16.h>
#include <math.h>

// Problem constants
#define NB 64
#define NS 512
#define NPIX (NS * NS)          // 262144
#define HF_COUNT 245760.0f      // 512*512 - 128*128

// -------- scratch (device globals; no allocation allowed) --------
__device__ __half2 g_Bf[NB * NPIX];  // 67 MB: pass-1 output (fp16 complex), TRANSPOSED (row = u, col = y)
__device__ float   g_part[NB][256];  // per-(batch, row-pair) partial sums (deterministic)

// -------- complex helpers --------
static __device__ __forceinline__ float2 cadd(float2 a, float2 b) { return make_float2(a.x + b.x, a.y + b.y); }
static __device__ __forceinline__ float2 csub(float2 a, float2 b) { return make_float2(a.x - b.x, a.y - b.y); }
static __device__ __forceinline__ float2 cmul(float2 a, float2 w) {
    return make_float2(fmaf(a.x, w.x, -a.y * w.y), fmaf(a.x, w.y, a.y * w.x));
}

// DFT-8 (DIF internally, output in natural order X[0..7])
static __device__ __forceinline__ void dft8(const float2 a[8], float2 X[8]) {
    const float r = 0.70710678118654752440f;
    float2 s0 = cadd(a[0], a[4]), d0 = csub(a[0], a[4]);
    float2 s1 = cadd(a[1], a[5]), d1 = csub(a[1], a[5]);
    float2 s2 = cadd(a[2], a[6]), d2 = csub(a[2], a[6]);
    float2 s3 = cadd(a[3], a[7]), d3 = csub(a[3], a[7]);
    float2 d1t = make_float2(r * (d1.x + d1.y), r * (d1.y - d1.x));
    float2 d2t = make_float2(d2.y, -d2.x);
    float2 d3t = make_float2(r * (d3.y - d3.x), -r * (d3.x + d3.y));
    float2 u0 = cadd(s0, s2), u2 = csub(s0, s2);
    float2 u1 = cadd(s1, s3);
    float2 u3t = csub(s1, s3);
    float2 u3 = make_float2(u3t.y, -u3t.x);
    X[0] = cadd(u0, u1);  X[4] = csub(u0, u1);
    X[2] = cadd(u2, u3);  X[6] = csub(u2, u3);
    float2 v0 = cadd(d0, d2t), v2 = csub(d0, d2t);
    float2 v1 = cadd(d1t, d3t);
    float2 v3t = csub(d1t, d3t);
    float2 v3 = make_float2(v3t.y, -v3t.x);
    X[1] = cadd(v0, v1);  X[5] = csub(v0, v1);
    X[3] = cadd(v2, v3);  X[7] = csub(v2, v3);
}

static __device__ __forceinline__ float gray01(float r, float g, float b) {
    return (r * 0.299f + g * 0.587f + b * 0.114f + 1.0f) * 0.5f;
}

// twiddle w^k = exp(-2*pi*i*k/512) = cos(pi*k/256) - i*sin(pi*k/256)
static __device__ __forceinline__ float2 twiddle(int k) {
    float s, c;
    sincospif((float)k * (1.0f / 256.0f), &s, &c);
    return make_float2(c, -s);
}

#define PADIDX(i) ((i) + ((i) >> 3))

// -------- K1: fused gray + row-FFT + transposed fp16 write --------
// 8 FFTs (8 consecutive image rows of one batch) per 512-thread block.
__global__ void __launch_bounds__(512) k_fft1(const float* __restrict__ gen,
                                              const float* __restrict__ tgt) {
    __shared__ float2 tw[512];
    __shared__ float2 buf[8][576];   // 4608 float2; reused as tile[512][9] at the end

    int tid = threadIdx.x;
    tw[tid] = twiddle(tid);

    int f = tid >> 6;                 // FFT id within block (0..7)
    int j = tid & 63;                 // lane within FFT
    int b  = blockIdx.x >> 6;         // 64 blocks per batch
    int y0 = (blockIdx.x & 63) << 3;  // first image row of this block
    int y  = y0 + f;

    size_t gbase = (size_t)b * (3u * NPIX) + (size_t)y * NS;
    const float* gp = gen + gbase;
    const float* tp = tgt + gbase;

    float2 a[8], X[8];
    #pragma unroll
    for (int p = 0; p < 8; p++) {
        int x = p * 64 + j;
        float g0 = gp[x], g1 = gp[x + NPIX], g2 = gp[x + 2 * NPIX];
        float t0 = tp[x], t1 = tp[x + NPIX], t2 = tp[x + 2 * NPIX];
        a[p] = make_float2(gray01(g0, g1, g2), gray01(t0, t1, t2));
    }

    // stage 0 (L=1)
    dft8(a, X);
    #pragma unroll
    for (int q = 0; q < 8; q++) { int idx = j * 8 + q; buf[f][PADIDX(idx)] = X[q]; }
    __syncthreads();   // also covers twiddle table fill

    // stage 1 (L=8)
    #pragma unroll
    for (int p = 0; p < 8; p++) { int idx = p * 64 + j; a[p] = buf[f][PADIDX(idx)]; }
    __syncthreads();
    int k1 = j & 7, b1 = j >> 3;
    #pragma unroll
    for (int p = 1; p < 8; p++) a[p] = cmul(a[p], tw[(p * k1) << 3]);
    dft8(a, X);
    #pragma unroll
    for (int q = 0; q < 8; q++) { int idx = b1 * 64 + q * 8 + k1; buf[f][PADIDX(idx)] = X[q]; }
    __syncthreads();

    // stage 2 (L=64)
    #pragma unroll
    for (int p = 0; p < 8; p++) { int idx = p * 64 + j; a[p] = buf[f][PADIDX(idx)]; }
    __syncthreads();   // all buf reads done; safe to reuse as transpose tile
    #pragma unroll
    for (int p = 1; p < 8; p++) a[p] = cmul(a[p], tw[p * j]);
    dft8(a, X);

    // stage result into transpose tile: tile[u][f], padded stride 9
    float2* tile = &buf[0][0];
    #pragma unroll
    for (int q = 0; q < 8; q++) { int u = q * 64 + j; tile[u * 9 + f] = X[q]; }
    __syncthreads();

    // coalesced transposed fp16 write: 8 consecutive y per u = 32B sector
    int yo = tid & 7;          // y offset within block
    int ub = tid >> 3;         // 0..63
    __half2* dst = g_Bf + (size_t)b * NPIX + y0 + yo;
    #pragma unroll
    for (int i = 0; i < 8; i++) {
        int u = ub + i * 64;
        float2 z = tile[u * 9 + yo];
        dst[(size_t)u * NS] = __floats2half2_rn(z.x, z.y);
    }
}

// -------- K2: column FFT on conjugate-partner row pairs + fused PSD --------
__global__ void __launch_bounds__(128) k_fft2_psd() {
    __shared__ float2 tw[512];
    __shared__ float2 buf[2][576];
    __shared__ float2 res[2][512];
    __shared__ float  red[128];

    int tid = threadIdx.x;
    #pragma unroll
    for (int i = 0; i < 4; i++) tw[tid + i * 128] = twiddle(tid + i * 128);

    int v = blockIdx.x;            // 0..255
    int b = blockIdx.y;            // batch
    int f = tid >> 6;              // 0 or 1
    int j = tid & 63;
    int rA = v;
    int rB = (v == 0) ? 256 : 512 - v;
    int r  = f ? rB : rA;

    const __half2* rp = g_Bf + (size_t)b * NPIX + (size_t)r * NS;

    float2 a[8], X[8];
    #pragma unroll
    for (int p = 0; p < 8; p++) a[p] = __half22float2(rp[p * 64 + j]);

    dft8(a, X);
    #pragma unroll
    for (int q = 0; q < 8; q++) { int idx = j * 8 + q; buf[f][PADIDX(idx)] = X[q]; }
    __syncthreads();

    #pragma unroll
    for (int p = 0; p < 8; p++) { int idx = p * 64 + j; a[p] = buf[f][PADIDX(idx)]; }
    __syncthreads();
    int k1 = j & 7, b1 = j >> 3;
    #pragma unroll
    for (int p = 1; p < 8; p++) a[p] = cmul(a[p], tw[(p * k1) << 3]);
    dft8(a, X);
    #pragma unroll
    for (int q = 0; q < 8; q++) { int idx = b1 * 64 + q * 8 + k1; buf[f][PADIDX(idx)] = X[q]; }
    __syncthreads();

    #pragma unroll
    for (int p = 0; p < 8; p++) { int idx = p * 64 + j; a[p] = buf[f][PADIDX(idx)]; }
    #pragma unroll
    for (int p = 1; p < 8; p++) a[p] = cmul(a[p], tw[p * j]);
    dft8(a, X);
    #pragma unroll
    for (int q = 0; q < 8; q++) res[f][q * 64 + j] = X[q];
    __syncthreads();

    // PSD pairing: Z(u,v) with Z(512-u,512-v); both rows live in res[].
    bool self = (v == 0);
    bool lowA = (rA < 64) | (rA >= 448);
    bool lowB = (rB < 64) | (rB >= 448);

    float acc = 0.0f;
    #pragma unroll
    for (int it = 0; it < 8; it++) {
        int i = it * 128 + tid;        // 0..1023
        int s = i >> 9;                // 0 -> row rA, 1 -> row rB
        int e = i & 511;               // element (y-frequency)
        bool lowr = s ? lowB : lowA;
        bool lowe = (e < 64) | (e >= 448);
        if (lowr & lowe) continue;     // low-frequency box masked out

        float2 z1 = res[s][e];
        int ps = self ? s : (1 - s);
        float2 z2 = res[ps][(512 - e) & 511];

        float ra = 0.5f * (z1.x + z2.x), ia = 0.5f * (z1.y - z2.y);
        float rb = 0.5f * (z1.y + z2.y), ib = 0.5f * (z2.x - z1.x);
        float pa = fmaf(ra, ra, ia * ia) + 1e-10f;
        float pb = fmaf(rb, rb, ib * ib) + 1e-10f;
        acc += __log2f(pa) - __log2f(pb);   // log10 factor applied at the end
    }

    red[tid] = acc;
    __syncthreads();
    #pragma unroll
    for (int s2 = 64; s2 > 0; s2 >>= 1) {
        if (tid < s2) red[tid] += red[tid + s2];
        __syncthreads();
    }
    if (tid == 0) g_part[b][v] = red[0];   // no atomics -> deterministic
}

// -------- K3: finalize (parallel, coalesced, deterministic) --------
// 1024 threads: thread t sums 16 values of batch t>>4 at offsets (t&15)+16k
// (coalesced across lanes, MLP=16), then a fixed-order smem combine.
__global__ void __launch_bounds__(1024) k_final(float* __restrict__ out) {
    int t = threadIdx.x;
    int b = t >> 4, i = t & 15;
    float s = 0.0f;
    #pragma unroll
    for (int k = 0; k < 16; k++) s += g_part[b][i + k * 16];

    __shared__ float sh[64][17];
    __shared__ float red[64];
    sh[b][i] = s;
    __syncthreads();

    if (t < 64) {
        float d = 0.0f;
        #pragma unroll
        for (int k = 0; k < 16; k++) d += sh[t][k];
        red[t] = fabsf(d);
    }
    __syncthreads();
    #pragma unroll
    for (int s2 = 32; s2 > 0; s2 >>= 1) {
        if (t < s2) red[t] += red[t + s2];
        __syncthreads();
    }
    if (t == 0) out[0] = red[0] * (0.30102999566398119521f / (HF_COUNT * 64.0f));
}

// -------- launch --------
extern "C" void kernel_launch(void* const* d_in, const int* in_sizes, int n_in,
                              void* d_out, int out_size) {
    const float* gen = (const float*)d_in[0];
    const float* tgt = (const float*)d_in[1];
    float* out = (float*)d_out;
    (void)in_sizes; (void)n_in; (void)out_size;

    k_fft1<<<NB * 64, 512>>>(gen, tgt);        // fused gray + row FFT + transpose
    {
        dim3 g(256, NB);
        k_fft2_psd<<<g, 128>>>();              // column FFT + fused PSD
    }
    k_final<<<1, 1024>>>(out);
}

// round 4
// speedup vs baseline: 1.8888x; 1.0047x over previous
#include <cuda_runtime.h>
#include <cuda_fp16.h>
#include <math.h>

// Problem constants
#define NB 64
#define NS 512
#define NPIX (NS * NS)          // 262144
#define HF_COUNT 245760.0f      // 512*512 - 128*128

// -------- scratch (device globals; no allocation allowed) --------
__device__ __half2 g_Bf[NB * NPIX];  // 67 MB: pass-1 output (fp16 complex), TRANSPOSED (row = u, col = y)
__device__ float   g_part[NB][256];  // per-(batch, v-pair) partial sums (deterministic)

// -------- complex helpers --------
static __device__ __forceinline__ float2 cadd(float2 a, float2 b) { return make_float2(a.x + b.x, a.y + b.y); }
static __device__ __forceinline__ float2 csub(float2 a, float2 b) { return make_float2(a.x - b.x, a.y - b.y); }
static __device__ __forceinline__ float2 cmul(float2 a, float2 w) {
    return make_float2(fmaf(a.x, w.x, -a.y * w.y), fmaf(a.x, w.y, a.y * w.x));
}

// DFT-8 (DIF internally, output in natural order X[0..7])
static __device__ __forceinline__ void dft8(const float2 a[8], float2 X[8]) {
    const float r = 0.70710678118654752440f;
    float2 s0 = cadd(a[0], a[4]), d0 = csub(a[0], a[4]);
    float2 s1 = cadd(a[1], a[5]), d1 = csub(a[1], a[5]);
    float2 s2 = cadd(a[2], a[6]), d2 = csub(a[2], a[6]);
    float2 s3 = cadd(a[3], a[7]), d3 = csub(a[3], a[7]);
    float2 d1t = make_float2(r * (d1.x + d1.y), r * (d1.y - d1.x));
    float2 d2t = make_float2(d2.y, -d2.x);
    float2 d3t = make_float2(r * (d3.y - d3.x), -r * (d3.x + d3.y));
    float2 u0 = cadd(s0, s2), u2 = csub(s0, s2);
    float2 u1 = cadd(s1, s3);
    float2 u3t = csub(s1, s3);
    float2 u3 = make_float2(u3t.y, -u3t.x);
    X[0] = cadd(u0, u1);  X[4] = csub(u0, u1);
    X[2] = cadd(u2, u3);  X[6] = csub(u2, u3);
    float2 v0 = cadd(d0, d2t), v2 = csub(d0, d2t);
    float2 v1 = cadd(d1t, d3t);
    float2 v3t = csub(d1t, d3t);
    float2 v3 = make_float2(v3t.y, -v3t.x);
    X[1] = cadd(v0, v1);  X[5] = csub(v0, v1);
    X[3] = cadd(v2, v3);  X[7] = csub(v2, v3);
}

static __device__ __forceinline__ float gray01(float r, float g, float b) {
    return (r * 0.299f + g * 0.587f + b * 0.114f + 1.0f) * 0.5f;
}

// twiddle w^k = exp(-2*pi*i*k/512) = cos(pi*k/256) - i*sin(pi*k/256)
static __device__ __forceinline__ float2 twiddle(int k) {
    float s, c;
    sincospif((float)k * (1.0f / 256.0f), &s, &c);
    return make_float2(c, -s);
}

#define PADIDX(i) ((i) + ((i) >> 3))

// -------- K1: fused gray + row-FFT + transposed fp16 write --------
// 16 FFTs (16 consecutive image rows of one batch) per 1024-thread block.
// Dynamic smem: buf[16][576] float2 (73728 B), reused as tile[512][17] float2.
__global__ void __launch_bounds__(1024, 2) k_fft1(const float* __restrict__ gen,
                                                  const float* __restrict__ tgt) {
    __shared__ float2 tw[512];
    extern __shared__ float2 dyn[];     // 16*576 float2

    int tid = threadIdx.x;
    if (tid < 512) tw[tid] = twiddle(tid);

    int f = tid >> 6;                 // FFT id within block (0..15)
    int j = tid & 63;                 // lane within FFT
    int b  = blockIdx.x >> 5;         // 32 blocks per batch
    int y0 = (blockIdx.x & 31) << 4;  // first image row of this block
    int y  = y0 + f;
    float2* buf = dyn + f * 576;

    size_t gbase = (size_t)b * (3u * NPIX) + (size_t)y * NS;
    const float* gp = gen + gbase;
    const float* tp = tgt + gbase;

    float2 a[8], X[8];
    #pragma unroll
    for (int p = 0; p < 8; p++) {
        int x = p * 64 + j;
        float g0 = gp[x], g1 = gp[x + NPIX], g2 = gp[x + 2 * NPIX];
        float t0 = tp[x], t1 = tp[x + NPIX], t2 = tp[x + 2 * NPIX];
        a[p] = make_float2(gray01(g0, g1, g2), gray01(t0, t1, t2));
    }

    // stage 0 (L=1)
    dft8(a, X);
    #pragma unroll
    for (int q = 0; q < 8; q++) { int idx = j * 8 + q; buf[PADIDX(idx)] = X[q]; }
    __syncthreads();   // also covers twiddle fill

    // stage 1 (L=8)
    #pragma unroll
    for (int p = 0; p < 8; p++) { int idx = p * 64 + j; a[p] = buf[PADIDX(idx)]; }
    __syncthreads();
    int k1 = j & 7, b1 = j >> 3;
    #pragma unroll
    for (int p = 1; p < 8; p++) a[p] = cmul(a[p], tw[(p * k1) << 3]);
    dft8(a, X);
    #pragma unroll
    for (int q = 0; q < 8; q++) { int idx = b1 * 64 + q * 8 + k1; buf[PADIDX(idx)] = X[q]; }
    __syncthreads();

    // stage 2 (L=64)
    #pragma unroll
    for (int p = 0; p < 8; p++) { int idx = p * 64 + j; a[p] = buf[PADIDX(idx)]; }
    __syncthreads();   // all buf reads done; safe to reuse dyn as transpose tile
    #pragma unroll
    for (int p = 1; p < 8; p++) a[p] = cmul(a[p], tw[p * j]);
    dft8(a, X);

    // stage result into transpose tile: tile[u*17 + f]
    float2* tile = dyn;
    #pragma unroll
    for (int q = 0; q < 8; q++) { int u = q * 64 + j; tile[u * 17 + f] = X[q]; }
    __syncthreads();

    // coalesced transposed fp16 write: 16 consecutive y per u = 64B chunks
    int yo = tid & 15;         // y offset within block
    int ub = tid >> 4;         // 0..63
    __half2* dst = g_Bf + (size_t)b * NPIX + y0 + yo;
    #pragma unroll
    for (int i = 0; i < 8; i++) {
        int u = ub + i * 64;
        float2 z = tile[u * 17 + yo];
        dst[(size_t)u * NS] = __floats2half2_rn(z.x, z.y);
    }
}

// -------- K2: column FFT on conjugate-partner row pairs + fused PSD --------
// 512 threads, 4 v-pairs (8 row FFTs) per block. grid (64, NB).
// Sub-block s = tid>>7 handles v = blockIdx.x*4 + s.
__global__ void __launch_bounds__(512, 3) k_fft2_psd() {
    __shared__ float2 tw[512];
    __shared__ float2 buf2[8][576];   // 36864 B; tail reused as res[8][512]
    __shared__ float  wsum[16];

    int tid = threadIdx.x;
    tw[tid] = twiddle(tid);

    int s    = tid >> 7;           // sub-block 0..3
    int tid2 = tid & 127;
    int f    = tid2 >> 6;          // 0 or 1 within pair
    int j    = tid2 & 63;
    int b    = blockIdx.y;
    int v    = blockIdx.x * 4 + s; // 0..255
    int rA = v;
    int rB = (v == 0) ? 256 : 512 - v;
    int r  = f ? rB : rA;
    float2* buf = &buf2[s * 2 + f][0];
    float2* res = &buf2[0][0];     // res[(s*2+h)*512 + e], 32768 B <= 36864 B

    const __half2* rp = g_Bf + (size_t)b * NPIX + (size_t)r * NS;

    float2 a[8], X[8];
    #pragma unroll
    for (int p = 0; p < 8; p++) a[p] = __half22float2(rp[p * 64 + j]);

    dft8(a, X);
    #pragma unroll
    for (int q = 0; q < 8; q++) { int idx = j * 8 + q; buf[PADIDX(idx)] = X[q]; }
    __syncthreads();

    #pragma unroll
    for (int p = 0; p < 8; p++) { int idx = p * 64 + j; a[p] = buf[PADIDX(idx)]; }
    __syncthreads();
    int k1 = j & 7, b1 = j >> 3;
    #pragma unroll
    for (int p = 1; p < 8; p++) a[p] = cmul(a[p], tw[(p * k1) << 3]);
    dft8(a, X);
    #pragma unroll
    for (int q = 0; q < 8; q++) { int idx = b1 * 64 + q * 8 + k1; buf[PADIDX(idx)] = X[q]; }
    __syncthreads();

    #pragma unroll
    for (int p = 0; p < 8; p++) { int idx = p * 64 + j; a[p] = buf[PADIDX(idx)]; }
    __syncthreads();   // all buf reads done; safe to overwrite as res
    #pragma unroll
    for (int p = 1; p < 8; p++) a[p] = cmul(a[p], tw[p * j]);
    dft8(a, X);
    #pragma unroll
    for (int q = 0; q < 8; q++) res[(s * 2 + f) * 512 + q * 64 + j] = X[q];
    __syncthreads();

    // PSD pairing: Z(u,e) with Z(512-u, 512-e); both rows of this pair in res.
    bool self = (v == 0);
    bool lowA = (rA < 64) | (rA >= 448);
    bool lowB = (rB < 64) | (rB >= 448);

    float acc = 0.0f;
    #pragma unroll
    for (int it = 0; it < 8; it++) {
        int i = it * 128 + tid2;       // 0..1023 over the pair's 2 rows
        int h = i >> 9;                // 0 -> row rA, 1 -> row rB
        int e = i & 511;               // y-frequency
        bool lowr = h ? lowB : lowA;
        bool lowe = (e < 64) | (e >= 448);
        if (lowr & lowe) continue;     // low-frequency box masked out

        float2 z1 = res[(s * 2 + h) * 512 + e];
        int ps = self ? h : (1 - h);
        float2 z2 = res[(s * 2 + ps) * 512 + ((512 - e) & 511)];

        float ra = 0.5f * (z1.x + z2.x), ia = 0.5f * (z1.y - z2.y);
        float rb = 0.5f * (z1.y + z2.y), ib = 0.5f * (z2.x - z1.x);
        float pa = fmaf(ra, ra, ia * ia) + 1e-10f;
        float pb = fmaf(rb, rb, ib * ib) + 1e-10f;
        acc += __log2f(pa) - __log2f(pb);   // log10 factor applied at the end
    }

    // warp reduce (fixed order -> deterministic), then 4 warps per sub-block
    #pragma unroll
    for (int o = 16; o > 0; o >>= 1) acc += __shfl_down_sync(0xFFFFFFFFu, acc, o);
    if ((tid & 31) == 0) wsum[tid >> 5] = acc;
    __syncthreads();
    if (tid < 4) {
        int ss = tid;
        float d = wsum[ss * 4] + wsum[ss * 4 + 1] + wsum[ss * 4 + 2] + wsum[ss * 4 + 3];
        g_part[b][blockIdx.x * 4 + ss] = d;   // no atomics -> deterministic
    }
}

// -------- K3: finalize (parallel, coalesced, deterministic) --------
__global__ void __launch_bounds__(1024) k_final(float* __restrict__ out) {
    int t = threadIdx.x;
    int b = t >> 4, i = t & 15;
    float s = 0.0f;
    #pragma unroll
    for (int k = 0; k < 16; k++) s += g_part[b][i + k * 16];

    __shared__ float sh[64][17];
    __shared__ float red[64];
    sh[b][i] = s;
    __syncthreads();

    if (t < 64) {
        float d = 0.0f;
        #pragma unroll
        for (int k = 0; k < 16; k++) d += sh[t][k];
        red[t] = fabsf(d);
    }
    __syncthreads();
    #pragma unroll
    for (int s2 = 32; s2 > 0; s2 >>= 1) {
        if (t < s2) red[t] += red[t + s2];
        __syncthreads();
    }
    if (t == 0) out[0] = red[0] * (0.30102999566398119521f / (HF_COUNT * 64.0f));
}

// -------- launch --------
extern "C" void kernel_launch(void* const* d_in, const int* in_sizes, int n_in,
                              void* d_out, int out_size) {
    const float* gen = (const float*)d_in[0];
    const float* tgt = (const float*)d_in[1];
    float* out = (float*)d_out;
    (void)in_sizes; (void)n_in; (void)out_size;

    const int FFT1_SMEM = 16 * 576 * sizeof(float2);   // 73728 B
    cudaFuncSetAttribute(k_fft1, cudaFuncAttributeMaxDynamicSharedMemorySize, FFT1_SMEM);

    k_fft1<<<NB * 32, 1024, FFT1_SMEM>>>(gen, tgt);   // fused gray + row FFT + transpose
    {
        dim3 g(64, NB);
        k_fft2_psd<<<g, 512>>>();                     // column FFT + fused PSD
    }
    k_final<<<1, 1024>>>(out);
}

// round 5
// speedup vs baseline: 1.9585x; 1.0369x over previous
#include <cuda_runtime.h>
#include <cuda_fp16.h>
#include <math.h>

// Problem constants
#define NB 64
#define NS 512
#define NPIX (NS * NS)          // 262144
#define HF_COUNT 245760.0f      // 512*512 - 128*128

// -------- scratch (device globals; no allocation allowed) --------
__device__ __half2 g_Bf[NB * NPIX];  // 67 MB: pass-1 output (fp16 complex), TRANSPOSED (row = u, col = y)
__device__ float2  g_tw[512];        // twiddles w^k = exp(-2*pi*i*k/512)
__device__ float   g_part[NB][256];  // per-(batch, v-pair) partial sums (deterministic)

// -------- complex helpers --------
static __device__ __forceinline__ float2 cadd(float2 a, float2 b) { return make_float2(a.x + b.x, a.y + b.y); }
static __device__ __forceinline__ float2 csub(float2 a, float2 b) { return make_float2(a.x - b.x, a.y - b.y); }
static __device__ __forceinline__ float2 cmul(float2 a, float2 w) {
    return make_float2(fmaf(a.x, w.x, -a.y * w.y), fmaf(a.x, w.y, a.y * w.x));
}

// DFT-8 (DIF internally, output in natural order X[0..7])
static __device__ __forceinline__ void dft8(const float2 a[8], float2 X[8]) {
    const float r = 0.70710678118654752440f;
    float2 s0 = cadd(a[0], a[4]), d0 = csub(a[0], a[4]);
    float2 s1 = cadd(a[1], a[5]), d1 = csub(a[1], a[5]);
    float2 s2 = cadd(a[2], a[6]), d2 = csub(a[2], a[6]);
    float2 s3 = cadd(a[3], a[7]), d3 = csub(a[3], a[7]);
    float2 d1t = make_float2(r * (d1.x + d1.y), r * (d1.y - d1.x));
    float2 d2t = make_float2(d2.y, -d2.x);
    float2 d3t = make_float2(r * (d3.y - d3.x), -r * (d3.x + d3.y));
    float2 u0 = cadd(s0, s2), u2 = csub(s0, s2);
    float2 u1 = cadd(s1, s3);
    float2 u3t = csub(s1, s3);
    float2 u3 = make_float2(u3t.y, -u3t.x);
    X[0] = cadd(u0, u1);  X[4] = csub(u0, u1);
    X[2] = cadd(u2, u3);  X[6] = csub(u2, u3);
    float2 v0 = cadd(d0, d2t), v2 = csub(d0, d2t);
    float2 v1 = cadd(d1t, d3t);
    float2 v3t = csub(d1t, d3t);
    float2 v3 = make_float2(v3t.y, -v3t.x);
    X[1] = cadd(v0, v1);  X[5] = csub(v0, v1);
    X[3] = cadd(v2, v3);  X[7] = csub(v2, v3);
}

static __device__ __forceinline__ float gray01(float r, float g, float b) {
    return (r * 0.299f + g * 0.587f + b * 0.114f + 1.0f) * 0.5f;
}

// -------- K0: twiddle table init (one tiny launch; blocks then just load it) --------
__global__ void k_init() {
    int t = threadIdx.x;
    double ang = -6.2831853071795864769252867665590058 * (double)t / 512.0;
    g_tw[t] = make_float2((float)cos(ang), (float)sin(ang));
}

#define PADIDX(i) ((i) + ((i) >> 3))

// -------- K1: fused gray + row-FFT + transposed fp16 write --------
// 8 FFTs (8 consecutive image rows of one batch) per 512-thread block.
__global__ void __launch_bounds__(512) k_fft1(const float* __restrict__ gen,
                                              const float* __restrict__ tgt) {
    __shared__ float2 tw[512];
    __shared__ float2 buf[8][576];   // 4608 float2; reused as tile[512][9] at the end

    int tid = threadIdx.x;
    tw[tid] = g_tw[tid];

    int f = tid >> 6;                 // FFT id within block (0..7)
    int j = tid & 63;                 // lane within FFT
    int b  = blockIdx.x >> 6;         // 64 blocks per batch
    int y0 = (blockIdx.x & 63) << 3;  // first image row of this block
    int y  = y0 + f;

    size_t gbase = (size_t)b * (3u * NPIX) + (size_t)y * NS;
    const float* gp = gen + gbase;
    const float* tp = tgt + gbase;

    float2 a[8], X[8];
    #pragma unroll
    for (int p = 0; p < 8; p++) {
        int x = p * 64 + j;
        float g0 = gp[x], g1 = gp[x + NPIX], g2 = gp[x + 2 * NPIX];
        float t0 = tp[x], t1 = tp[x + NPIX], t2 = tp[x + 2 * NPIX];
        a[p] = make_float2(gray01(g0, g1, g2), gray01(t0, t1, t2));
    }

    // stage 0 (L=1)
    dft8(a, X);
    #pragma unroll
    for (int q = 0; q < 8; q++) { int idx = j * 8 + q; buf[f][PADIDX(idx)] = X[q]; }
    __syncthreads();   // also covers twiddle table fill

    // stage 1 (L=8)
    #pragma unroll
    for (int p = 0; p < 8; p++) { int idx = p * 64 + j; a[p] = buf[f][PADIDX(idx)]; }
    __syncthreads();
    int k1 = j & 7, b1 = j >> 3;
    #pragma unroll
    for (int p = 1; p < 8; p++) a[p] = cmul(a[p], tw[(p * k1) << 3]);
    dft8(a, X);
    #pragma unroll
    for (int q = 0; q < 8; q++) { int idx = b1 * 64 + q * 8 + k1; buf[f][PADIDX(idx)] = X[q]; }
    __syncthreads();

    // stage 2 (L=64)
    #pragma unroll
    for (int p = 0; p < 8; p++) { int idx = p * 64 + j; a[p] = buf[f][PADIDX(idx)]; }
    __syncthreads();   // all buf reads done; safe to reuse as transpose tile
    #pragma unroll
    for (int p = 1; p < 8; p++) a[p] = cmul(a[p], tw[p * j]);
    dft8(a, X);

    // stage result into transpose tile: tile[u][f], padded stride 9
    float2* tile = &buf[0][0];
    #pragma unroll
    for (int q = 0; q < 8; q++) { int u = q * 64 + j; tile[u * 9 + f] = X[q]; }
    __syncthreads();

    // coalesced transposed fp16 write: 8 consecutive y per u = 32B sector
    int yo = tid & 7;          // y offset within block
    int ub = tid >> 3;         // 0..63
    __half2* dst = g_Bf + (size_t)b * NPIX + y0 + yo;
    #pragma unroll
    for (int i = 0; i < 8; i++) {
        int u = ub + i * 64;
        float2 z = tile[u * 9 + yo];
        dst[(size_t)u * NS] = __floats2half2_rn(z.x, z.y);
    }
}

// -------- K2: column FFT on conjugate-partner row pairs + fused PSD --------
// 256 threads, 2 v-pairs (4 row FFTs) per block. grid (128, NB).
__global__ void __launch_bounds__(256) k_fft2_psd() {
    __shared__ float2 tw[512];
    __shared__ float2 buf2[4][576];   // 18432 B; reused as res[4][512] (16384 B)
    __shared__ float  wsum[8];

    int tid = threadIdx.x;
    tw[tid] = g_tw[tid];
    tw[tid + 256] = g_tw[tid + 256];

    int s    = tid >> 7;           // sub-block (pair) 0..1
    int tid2 = tid & 127;
    int f    = tid2 >> 6;          // 0 or 1 within pair
    int j    = tid2 & 63;
    int b    = blockIdx.y;
    int v    = blockIdx.x * 2 + s; // 0..255
    int rA = v;
    int rB = (v == 0) ? 256 : 512 - v;
    int r  = f ? rB : rA;
    float2* buf = &buf2[s * 2 + f][0];
    float2* res = &buf2[0][0];     // res[(s*2+h)*512 + e]

    const __half2* rp = g_Bf + (size_t)b * NPIX + (size_t)r * NS;

    float2 a[8], X[8];
    #pragma unroll
    for (int p = 0; p < 8; p++) a[p] = __half22float2(rp[p * 64 + j]);

    dft8(a, X);
    #pragma unroll
    for (int q = 0; q < 8; q++) { int idx = j * 8 + q; buf[PADIDX(idx)] = X[q]; }
    __syncthreads();

    #pragma unroll
    for (int p = 0; p < 8; p++) { int idx = p * 64 + j; a[p] = buf[PADIDX(idx)]; }
    __syncthreads();
    int k1 = j & 7, b1 = j >> 3;
    #pragma unroll
    for (int p = 1; p < 8; p++) a[p] = cmul(a[p], tw[(p * k1) << 3]);
    dft8(a, X);
    #pragma unroll
    for (int q = 0; q < 8; q++) { int idx = b1 * 64 + q * 8 + k1; buf[PADIDX(idx)] = X[q]; }
    __syncthreads();

    #pragma unroll
    for (int p = 0; p < 8; p++) { int idx = p * 64 + j; a[p] = buf[PADIDX(idx)]; }
    __syncthreads();   // all buf reads done; safe to overwrite as res
    #pragma unroll
    for (int p = 1; p < 8; p++) a[p] = cmul(a[p], tw[p * j]);
    dft8(a, X);
    #pragma unroll
    for (int q = 0; q < 8; q++) res[(s * 2 + f) * 512 + q * 64 + j] = X[q];
    __syncthreads();

    // PSD pairing: Z(u,e) with Z(512-u, 512-e); both rows of this pair in res.
    bool self = (v == 0);
    bool lowA = (rA < 64) | (rA >= 448);
    bool lowB = (rB < 64) | (rB >= 448);

    float acc = 0.0f;
    #pragma unroll
    for (int it = 0; it < 8; it++) {
        int i = it * 128 + tid2;       // 0..1023 over the pair's 2 rows
        int h = i >> 9;                // 0 -> row rA, 1 -> row rB
        int e = i & 511;               // y-frequency
        bool lowr = h ? lowB : lowA;
        bool lowe = (e < 64) | (e >= 448);
        if (lowr & lowe) continue;     // low-frequency box masked out

        float2 z1 = res[(s * 2 + h) * 512 + e];
        int ps = self ? h : (1 - h);
        float2 z2 = res[(s * 2 + ps) * 512 + ((512 - e) & 511)];

        float ra = 0.5f * (z1.x + z2.x), ia = 0.5f * (z1.y - z2.y);
        float rb = 0.5f * (z1.y + z2.y), ib = 0.5f * (z2.x - z1.x);
        float pa = fmaf(ra, ra, ia * ia) + 1e-10f;
        float pb = fmaf(rb, rb, ib * ib) + 1e-10f;
        acc += __log2f(pa) - __log2f(pb);   // log10 factor applied at the end
    }

    // warp reduce (fixed order -> deterministic), then 4 warps per sub-block
    #pragma unroll
    for (int o = 16; o > 0; o >>= 1) acc += __shfl_down_sync(0xFFFFFFFFu, acc, o);
    if ((tid & 31) == 0) wsum[tid >> 5] = acc;
    __syncthreads();
    if (tid < 2) {
        int ss = tid;
        float d = wsum[ss * 4] + wsum[ss * 4 + 1] + wsum[ss * 4 + 2] + wsum[ss * 4 + 3];
        g_part[b][blockIdx.x * 2 + ss] = d;   // no atomics -> deterministic
    }
}

// -------- K3: finalize (parallel, coalesced, deterministic) --------
__global__ void __launch_bounds__(1024) k_final(float* __restrict__ out) {
    int t = threadIdx.x;
    int b = t >> 4, i = t & 15;
    float s = 0.0f;
    #pragma unroll
    for (int k = 0; k < 16; k++) s += g_part[b][i + k * 16];

    __shared__ float sh[64][17];
    __shared__ float red[64];
    sh[b][i] = s;
    __syncthreads();

    if (t < 64) {
        float d = 0.0f;
        #pragma unroll
        for (int k = 0; k < 16; k++) d += sh[t][k];
        red[t] = fabsf(d);
    }
    __syncthreads();
    #pragma unroll
    for (int s2 = 32; s2 > 0; s2 >>= 1) {
        if (t < s2) red[t] += red[t + s2];
        __syncthreads();
    }
    if (t == 0) out[0] = red[0] * (0.30102999566398119521f / (HF_COUNT * 64.0f));
}

// -------- launch --------
extern "C" void kernel_launch(void* const* d_in, const int* in_sizes, int n_in,
                              void* d_out, int out_size) {
    const float* gen = (const float*)d_in[0];
    const float* tgt = (const float*)d_in[1];
    float* out = (float*)d_out;
    (void)in_sizes; (void)n_in; (void)out_size;

    k_init<<<1, 512>>>();
    k_fft1<<<NB * 64, 512>>>(gen, tgt);        // fused gray + row FFT + transpose
    {
        dim3 g(128, NB);
        k_fft2_psd<<<g, 256>>>();              // column FFT + fused PSD
    }
    k_final<<<1, 1024>>>(out);
}